// round 9
// baseline (speedup 1.0000x reference)
#include <cuda_runtime.h>
#include <math_constants.h>

#define GRID 128
#define NCELLS (GRID * GRID)     // 16384
#define MAXN2 16384
#define NB 128                   // blocks (must be co-resident; 148 SMs)
#define NT 256                   // threads per block
#define CPB (NCELLS / NB)        // 128 cells per block

// ---------------- device scratch (no allocations allowed) ----------------
__device__ int    g_count[NCELLS];
__device__ int    g_start[NCELLS];
__device__ int    g_cursor[NCELLS];
__device__ float2 g_sorted[MAXN2];
__device__ float  g_bxm[NB], g_bym[NB], g_bxM[NB], g_byM[NB];
__device__ int    g_bsum[NB];
__device__ float  g_blocksums[NB];
__device__ int    g_bar_count = 0;
__device__ int    g_bar_gen   = 0;

// ---------------- software grid barrier (generation counter) ----------------
__device__ __forceinline__ void grid_barrier()
{
    __syncthreads();
    if (threadIdx.x == 0) {
        __threadfence();
        const int gen = *((volatile int*)&g_bar_gen);
        if (atomicAdd(&g_bar_count, 1) == NB - 1) {
            atomicExch(&g_bar_count, 0);
            __threadfence();
            *((volatile int*)&g_bar_gen) = gen + 1;
        } else {
            while (*((volatile int*)&g_bar_gen) == gen) { }
            __threadfence();
        }
    }
    __syncthreads();
}

__device__ __forceinline__ int cell_of(float v, float v0, float s)
{
    int c = (int)((v - v0) * s);
    c = c < 0 ? 0 : c;
    return c > GRID - 1 ? GRID - 1 : c;
}

// 2-way unrolled scan of a contiguous candidate run
__device__ __forceinline__ void scan_run(int s, int e, float qx, float qy,
                                         float& b0, float& b1)
{
    int k = s;
    for (; k + 2 <= e; k += 2) {
        const float2 p0 = g_sorted[k];
        const float2 p1 = g_sorted[k + 1];
        const float dx0 = qx - p0.x, dy0 = qy - p0.y;
        const float dx1 = qx - p1.x, dy1 = qy - p1.y;
        b0 = fminf(b0, fmaf(dx0, dx0, dy0 * dy0));
        b1 = fminf(b1, fmaf(dx1, dx1, dy1 * dy1));
    }
    if (k < e) {
        const float2 p = g_sorted[k];
        const float dx = qx - p.x, dy = qy - p.y;
        b0 = fminf(b0, fmaf(dx, dx, dy * dy));
    }
}

// contiguous row segment of cells [xlo..xhi] in row y  -> one run
__device__ __forceinline__ void scan_row(int y, int xlo, int xhi,
                                         float qx, float qy, float& b0, float& b1)
{
    const int c0 = y * GRID + xlo;
    const int c1 = y * GRID + xhi;
    const int s = g_start[c0];
    const int e = g_start[c1] + g_count[c1];
    scan_run(s, e, qx, qy, b0, b1);
}

// ================= the single fused kernel =================
__global__ void __launch_bounds__(NT) nn_fused(
    const float* __restrict__ pos1,
    const float* __restrict__ pos2,
    float* __restrict__ out,
    int N1, int N2)
{
    __shared__ float s_ax[NT], s_ay[NT], s_bx[NT], s_by[NT];
    __shared__ int   s_scan[NT];
    __shared__ float s_box[5];
    __shared__ int   s_off;

    const int tid = threadIdx.x;
    const int b   = blockIdx.x;
    const int gid = b * NT + tid;
    const int gstride = NB * NT;

    // ---------- Phase 0: zero counts + bbox block-partials ----------
    for (int c = gid; c < NCELLS; c += gstride) g_count[c] = 0;

    {
        float xm = CUDART_INF_F, ym = CUDART_INF_F;
        float xM = -CUDART_INF_F, yM = -CUDART_INF_F;
        for (int i = gid; i < N2 && i < MAXN2; i += gstride) {
            const float2 p = reinterpret_cast<const float2*>(pos2)[i];
            xm = fminf(xm, p.x); xM = fmaxf(xM, p.x);
            ym = fminf(ym, p.y); yM = fmaxf(yM, p.y);
        }
        s_ax[tid] = xm; s_ay[tid] = ym; s_bx[tid] = xM; s_by[tid] = yM;
        __syncthreads();
        for (int s = NT / 2; s > 0; s >>= 1) {
            if (tid < s) {
                s_ax[tid] = fminf(s_ax[tid], s_ax[tid + s]);
                s_ay[tid] = fminf(s_ay[tid], s_ay[tid + s]);
                s_bx[tid] = fmaxf(s_bx[tid], s_bx[tid + s]);
                s_by[tid] = fmaxf(s_by[tid], s_by[tid + s]);
            }
            __syncthreads();
        }
        if (tid == 0) {
            g_bxm[b] = s_ax[0]; g_bym[b] = s_ay[0];
            g_bxM[b] = s_bx[0]; g_byM[b] = s_by[0];
        }
    }
    grid_barrier();   // (1)

    // ---------- Phase 1: finalize box (redundant per block) + count ----------
    {
        s_ax[tid] = (tid < NB) ? g_bxm[tid] : CUDART_INF_F;
        s_ay[tid] = (tid < NB) ? g_bym[tid] : CUDART_INF_F;
        s_bx[tid] = (tid < NB) ? g_bxM[tid] : -CUDART_INF_F;
        s_by[tid] = (tid < NB) ? g_byM[tid] : -CUDART_INF_F;
        __syncthreads();
        for (int s = NT / 2; s > 0; s >>= 1) {
            if (tid < s) {
                s_ax[tid] = fminf(s_ax[tid], s_ax[tid + s]);
                s_ay[tid] = fminf(s_ay[tid], s_ay[tid + s]);
                s_bx[tid] = fmaxf(s_bx[tid], s_bx[tid + s]);
                s_by[tid] = fmaxf(s_by[tid], s_by[tid + s]);
            }
            __syncthreads();
        }
        if (tid == 0) {
            const float x0 = s_ax[0], y0 = s_ay[0];
            const float ex = fmaxf(s_bx[0] - x0, 1e-6f);
            const float ey = fmaxf(s_by[0] - y0, 1e-6f);
            s_box[0] = x0;
            s_box[1] = y0;
            s_box[2] = (float)GRID / ex;
            s_box[3] = (float)GRID / ey;
            s_box[4] = fminf(ex / (float)GRID, ey / (float)GRID);
        }
        __syncthreads();
    }
    const float x0 = s_box[0], y0 = s_box[1];
    const float sx = s_box[2], sy = s_box[3];
    const float cwmin = s_box[4];

    for (int i = gid; i < N2 && i < MAXN2; i += gstride) {
        const float2 p = reinterpret_cast<const float2*>(pos2)[i];
        const int cx = cell_of(p.x, x0, sx);
        const int cy = cell_of(p.y, y0, sy);
        atomicAdd(&g_count[cy * GRID + cx], 1);
    }
    grid_barrier();   // (2)

    // ---------- Phase 2: per-block scan of 128 cells ----------
    {
        int myc = 0;
        if (tid < CPB) myc = g_count[b * CPB + tid];
        s_scan[tid] = (tid < CPB) ? myc : 0;
        __syncthreads();
        for (int off = 1; off < CPB; off <<= 1) {
            int v = (tid >= off && tid < CPB) ? s_scan[tid - off] : 0;
            __syncthreads();
            if (tid < CPB) s_scan[tid] += v;
            __syncthreads();
        }
        if (tid < CPB) g_start[b * CPB + tid] = s_scan[tid] - myc;  // local exclusive
        if (tid == CPB - 1) g_bsum[b] = s_scan[tid];                // block total
    }
    grid_barrier();   // (3)

    // ---------- Phase 3: redundant scan of block totals + fixup ----------
    {
        s_scan[tid] = (tid < NB) ? g_bsum[tid] : 0;
        __syncthreads();
        for (int off = 1; off < NB; off <<= 1) {
            int v = (tid >= off && tid < NB) ? s_scan[tid - off] : 0;
            __syncthreads();
            if (tid < NB) s_scan[tid] += v;
            __syncthreads();
        }
        if (tid == 0) s_off = (b == 0) ? 0 : s_scan[b - 1];
        __syncthreads();
        const int off = s_off;
        if (tid < CPB) {
            const int base = g_start[b * CPB + tid] + off;
            g_start[b * CPB + tid]  = base;
            g_cursor[b * CPB + tid] = base;
        }
    }
    grid_barrier();   // (4)

    // ---------- Phase 4: scatter ----------
    for (int i = gid; i < N2 && i < MAXN2; i += gstride) {
        const float2 p = reinterpret_cast<const float2*>(pos2)[i];
        const int cx = cell_of(p.x, x0, sx);
        const int cy = cell_of(p.y, y0, sy);
        const int pos = atomicAdd(&g_cursor[cy * GRID + cx], 1);
        g_sorted[pos] = p;
    }
    grid_barrier();   // (5)

    // ---------- Phase 5: ring-search queries ----------
    {
        float acc = 0.0f;
        for (int i = gid; i < N1; i += gstride) {
            const float2 q = reinterpret_cast<const float2*>(pos1)[i];
            const int cx = cell_of(q.x, x0, sx);
            const int cy = cell_of(q.y, y0, sy);

            float b0 = CUDART_INF_F, b1 = CUDART_INF_F;
            // ring 0
            scan_row(cy, cx, cx, q.x, q.y, b0, b1);

            for (int r = 1; ; r++) {
                // rings 0..r-1 complete: unexamined cells at ring >= r
                // => min possible distance >= (r-1)*cwmin
                const float best = fminf(b0, b1);
                const float bd = (float)(r - 1) * cwmin;
                if (best <= bd * bd) break;
                const int rm = r - 1;
                if (cx - rm <= 0 && cy - rm <= 0 &&
                    cx + rm >= GRID - 1 && cy + rm >= GRID - 1) break;  // grid exhausted

                const int xlo = max(cx - r, 0), xhi = min(cx + r, GRID - 1);
                if (cy - r >= 0)          scan_row(cy - r, xlo, xhi, q.x, q.y, b0, b1);
                if (cy + r <= GRID - 1)   scan_row(cy + r, xlo, xhi, q.x, q.y, b0, b1);
                const int ylo = max(cy - r + 1, 0), yhi = min(cy + r - 1, GRID - 1);
                if (cx - r >= 0)
                    for (int y = ylo; y <= yhi; y++) scan_row(y, cx - r, cx - r, q.x, q.y, b0, b1);
                if (cx + r <= GRID - 1)
                    for (int y = ylo; y <= yhi; y++) scan_row(y, cx + r, cx + r, q.x, q.y, b0, b1);
            }
            acc += sqrtf(fminf(b0, b1));
        }

        s_ax[tid] = acc;
        __syncthreads();
        for (int s = NT / 2; s > 0; s >>= 1) {
            if (tid < s) s_ax[tid] += s_ax[tid + s];
            __syncthreads();
        }
        if (tid == 0) g_blocksums[b] = s_ax[0];
    }
    grid_barrier();   // (6)

    // ---------- Phase 6: final reduce (block 0) ----------
    if (b == 0) {
        s_ax[tid] = (tid < NB) ? g_blocksums[tid] : 0.0f;
        __syncthreads();
        for (int s = NT / 2; s > 0; s >>= 1) {
            if (tid < s) s_ax[tid] += s_ax[tid + s];
            __syncthreads();
        }
        if (tid == 0) out[0] = s_ax[0] / (float)N1;
    }
}

// ================= launch =================
extern "C" void kernel_launch(void* const* d_in, const int* in_sizes, int n_in,
                              void* d_out, int out_size)
{
    const float* pos1 = (const float*)d_in[0];
    const float* pos2 = (const float*)d_in[1];
    float* out = (float*)d_out;

    const int N1 = in_sizes[0] / 2;
    const int N2 = in_sizes[1] / 2;

    nn_fused<<<NB, NT>>>(pos1, pos2, out, N1, N2);
}

// round 11
// speedup vs baseline: 1.4578x; 1.4578x over previous
#include <cuda_runtime.h>
#include <math_constants.h>

#define GRID 128
#define NCELLS (GRID * GRID)     // 16384
#define MAXN2 16384
#define NB 256                   // blocks (co-resident: 2/SM on 148 SMs)
#define NT 256                   // threads per block
#define NWARP (NB * NT / 32)     // 2048 warps
#define CPB (NCELLS / NB)        // 64 cells per block

// ---------------- device scratch (no allocations allowed) ----------------
__device__ int    g_count[NCELLS];
__device__ int    g_start[NCELLS];
__device__ int    g_cursor[NCELLS];
__device__ float2 g_sorted[MAXN2];
__device__ float  g_bxm[NB], g_bym[NB], g_bxM[NB], g_byM[NB];
__device__ int    g_bsum[NB];
__device__ float  g_blocksums[NB];
__device__ int    g_bar_count = 0;
__device__ int    g_bar_gen   = 0;

// ---------------- software grid barrier (generation counter) ----------------
__device__ __forceinline__ void grid_barrier()
{
    __syncthreads();
    if (threadIdx.x == 0) {
        __threadfence();
        const int gen = *((volatile int*)&g_bar_gen);
        if (atomicAdd(&g_bar_count, 1) == NB - 1) {
            atomicExch(&g_bar_count, 0);
            __threadfence();
            *((volatile int*)&g_bar_gen) = gen + 1;
        } else {
            while (*((volatile int*)&g_bar_gen) == gen) { }
            __threadfence();
        }
    }
    __syncthreads();
}

__device__ __forceinline__ int cell_of(float v, float v0, float s)
{
    int c = (int)((v - v0) * s);
    c = c < 0 ? 0 : c;
    return c > GRID - 1 ? GRID - 1 : c;
}

// warp-cooperative scan of contiguous run [s, e): lanes stride, coalesced
__device__ __forceinline__ void scan_run_warp(int s, int e, int lane,
                                              float qx, float qy, float& best)
{
    for (int k = s + lane; k < e; k += 32) {
        const float2 p = g_sorted[k];
        const float dx = qx - p.x;
        const float dy = qy - p.y;
        best = fminf(best, fmaf(dx, dx, dy * dy));
    }
}

__device__ __forceinline__ float warp_min(float v)
{
#pragma unroll
    for (int off = 16; off > 0; off >>= 1)
        v = fminf(v, __shfl_xor_sync(0xffffffffu, v, off));
    return v;
}

// ================= the single fused kernel =================
__global__ void __launch_bounds__(NT, 2) nn_fused(
    const float* __restrict__ pos1,
    const float* __restrict__ pos2,
    float* __restrict__ out,
    int N1, int N2)
{
    __shared__ float s_ax[NT], s_ay[NT], s_bx[NT], s_by[NT];
    __shared__ int   s_scan[NT];
    __shared__ float s_box[5];
    __shared__ int   s_off;
    __shared__ float s_wsum[NT / 32];

    const int tid = threadIdx.x;
    const int b   = blockIdx.x;
    const int gid = b * NT + tid;
    const int gstride = NB * NT;
    const int lane = tid & 31;
    const int wid_g = (gid >> 5);          // global warp id

    // ---------- Phase 0: zero counts + bbox block-partials ----------
    for (int c = gid; c < NCELLS; c += gstride) g_count[c] = 0;

    {
        float xm = CUDART_INF_F, ym = CUDART_INF_F;
        float xM = -CUDART_INF_F, yM = -CUDART_INF_F;
        for (int i = gid; i < N2 && i < MAXN2; i += gstride) {
            const float2 p = reinterpret_cast<const float2*>(pos2)[i];
            xm = fminf(xm, p.x); xM = fmaxf(xM, p.x);
            ym = fminf(ym, p.y); yM = fmaxf(yM, p.y);
        }
        s_ax[tid] = xm; s_ay[tid] = ym; s_bx[tid] = xM; s_by[tid] = yM;
        __syncthreads();
        for (int s = NT / 2; s > 0; s >>= 1) {
            if (tid < s) {
                s_ax[tid] = fminf(s_ax[tid], s_ax[tid + s]);
                s_ay[tid] = fminf(s_ay[tid], s_ay[tid + s]);
                s_bx[tid] = fmaxf(s_bx[tid], s_bx[tid + s]);
                s_by[tid] = fmaxf(s_by[tid], s_by[tid + s]);
            }
            __syncthreads();
        }
        if (tid == 0) {
            g_bxm[b] = s_ax[0]; g_bym[b] = s_ay[0];
            g_bxM[b] = s_bx[0]; g_byM[b] = s_by[0];
        }
    }
    grid_barrier();   // (1)

    // ---------- Phase 1: finalize box (redundant per block) + count ----------
    {
        s_ax[tid] = (tid < NB) ? g_bxm[tid] : CUDART_INF_F;
        s_ay[tid] = (tid < NB) ? g_bym[tid] : CUDART_INF_F;
        s_bx[tid] = (tid < NB) ? g_bxM[tid] : -CUDART_INF_F;
        s_by[tid] = (tid < NB) ? g_byM[tid] : -CUDART_INF_F;
        __syncthreads();
        for (int s = NT / 2; s > 0; s >>= 1) {
            if (tid < s) {
                s_ax[tid] = fminf(s_ax[tid], s_ax[tid + s]);
                s_ay[tid] = fminf(s_ay[tid], s_ay[tid + s]);
                s_bx[tid] = fmaxf(s_bx[tid], s_bx[tid + s]);
                s_by[tid] = fmaxf(s_by[tid], s_by[tid + s]);
            }
            __syncthreads();
        }
        if (tid == 0) {
            const float x0 = s_ax[0], y0 = s_ay[0];
            const float ex = fmaxf(s_bx[0] - x0, 1e-6f);
            const float ey = fmaxf(s_by[0] - y0, 1e-6f);
            s_box[0] = x0;
            s_box[1] = y0;
            s_box[2] = (float)GRID / ex;
            s_box[3] = (float)GRID / ey;
            s_box[4] = fminf(ex / (float)GRID, ey / (float)GRID);
        }
        __syncthreads();
    }
    const float x0 = s_box[0], y0 = s_box[1];
    const float sx = s_box[2], sy = s_box[3];
    const float cwmin = s_box[4];

    for (int i = gid; i < N2 && i < MAXN2; i += gstride) {
        const float2 p = reinterpret_cast<const float2*>(pos2)[i];
        const int cx = cell_of(p.x, x0, sx);
        const int cy = cell_of(p.y, y0, sy);
        atomicAdd(&g_count[cy * GRID + cx], 1);
    }
    grid_barrier();   // (2)

    // ---------- Phase 2: per-block scan of CPB cells ----------
    {
        int myc = 0;
        if (tid < CPB) myc = g_count[b * CPB + tid];
        s_scan[tid] = (tid < CPB) ? myc : 0;
        __syncthreads();
        for (int off = 1; off < CPB; off <<= 1) {
            int v = (tid >= off && tid < CPB) ? s_scan[tid - off] : 0;
            __syncthreads();
            if (tid < CPB) s_scan[tid] += v;
            __syncthreads();
        }
        if (tid < CPB) g_start[b * CPB + tid] = s_scan[tid] - myc;  // local exclusive
        if (tid == CPB - 1) g_bsum[b] = s_scan[tid];                // block total
    }
    grid_barrier();   // (3)

    // ---------- Phase 3: redundant scan of block totals + fixup ----------
    {
        s_scan[tid] = (tid < NB) ? g_bsum[tid] : 0;
        __syncthreads();
        for (int off = 1; off < NB; off <<= 1) {
            int v = (tid >= off && tid < NB) ? s_scan[tid - off] : 0;
            __syncthreads();
            if (tid < NB) s_scan[tid] += v;
            __syncthreads();
        }
        if (tid == 0) s_off = (b == 0) ? 0 : s_scan[b - 1];
        __syncthreads();
        const int off = s_off;
        if (tid < CPB) {
            const int base = g_start[b * CPB + tid] + off;
            g_start[b * CPB + tid]  = base;
            g_cursor[b * CPB + tid] = base;
        }
    }
    grid_barrier();   // (4)

    // ---------- Phase 4: scatter ----------
    for (int i = gid; i < N2 && i < MAXN2; i += gstride) {
        const float2 p = reinterpret_cast<const float2*>(pos2)[i];
        const int cx = cell_of(p.x, x0, sx);
        const int cy = cell_of(p.y, y0, sy);
        const int pos = atomicAdd(&g_cursor[cy * GRID + cx], 1);
        g_sorted[pos] = p;
    }
    grid_barrier();   // (5)

    // ---------- Phase 5: warp-cooperative square-search queries ----------
    {
        float acc = 0.0f;   // identical across lanes of the warp
        for (int i = wid_g; i < N1; i += NWARP) {
            const float2 q = reinterpret_cast<const float2*>(pos1)[i];  // broadcast load
            const float qx = q.x, qy = q.y;
            const int cx = cell_of(qx, x0, sx);
            const int cy = cell_of(qy, y0, sy);

            float best = CUDART_INF_F;   // per-lane partial min

            // square r=1: rows cy-1..cy+1, each a contiguous run
            {
                const int xlo = max(cx - 1, 0), xhi = min(cx + 1, GRID - 1);
                const int ylo = max(cy - 1, 0), yhi = min(cy + 1, GRID - 1);
                for (int y = ylo; y <= yhi; y++) {
                    const int c0 = y * GRID + xlo;
                    const int c1 = y * GRID + xhi;
                    const int s = g_start[c0];
                    const int e = g_start[c1] + g_count[c1];
                    scan_run_warp(s, e, lane, qx, qy, best);
                }
            }

            float red = warp_min(best);
            for (int r = 1; ; r++) {
                // square radius r complete: unexamined cells at Chebyshev >= r+1
                // => min possible squared distance >= (r*cwmin)^2
                const float bd = (float)r * cwmin;
                if (red <= bd * bd) break;
                if (cx - r <= 0 && cy - r <= 0 &&
                    cx + r >= GRID - 1 && cy + r >= GRID - 1) break;  // grid exhausted

                const int rn = r + 1;
                const int xlo = max(cx - rn, 0), xhi = min(cx + rn, GRID - 1);
                // new full rows at cy +/- rn
                if (cy - rn >= 0) {
                    const int y = cy - rn;
                    const int s = g_start[y * GRID + xlo];
                    const int e = g_start[y * GRID + xhi] + g_count[y * GRID + xhi];
                    scan_run_warp(s, e, lane, qx, qy, best);
                }
                if (cy + rn <= GRID - 1) {
                    const int y = cy + rn;
                    const int s = g_start[y * GRID + xlo];
                    const int e = g_start[y * GRID + xhi] + g_count[y * GRID + xhi];
                    scan_run_warp(s, e, lane, qx, qy, best);
                }
                // new side cells at x = cx +/- rn for old rows
                const int ylo = max(cy - rn + 1, 0), yhi = min(cy + rn - 1, GRID - 1);
                if (cx - rn >= 0) {
                    for (int y = ylo; y <= yhi; y++) {
                        const int c = y * GRID + (cx - rn);
                        scan_run_warp(g_start[c], g_start[c] + g_count[c], lane, qx, qy, best);
                    }
                }
                if (cx + rn <= GRID - 1) {
                    for (int y = ylo; y <= yhi; y++) {
                        const int c = y * GRID + (cx + rn);
                        scan_run_warp(g_start[c], g_start[c] + g_count[c], lane, qx, qy, best);
                    }
                }
                red = warp_min(best);
            }
            acc += sqrtf(red);
        }

        // per-warp -> block reduce
        if (lane == 0) s_wsum[tid >> 5] = acc;
        __syncthreads();
        if (tid < NT / 32) {
            float v = s_wsum[tid];
            s_ax[tid] = v;
        }
        __syncthreads();
        if (tid == 0) {
            float v = 0.0f;
            for (int w = 0; w < NT / 32; w++) v += s_ax[w];
            g_blocksums[b] = v;
        }
    }
    grid_barrier();   // (6)

    // ---------- Phase 6: final reduce (block 0) ----------
    if (b == 0) {
        s_ax[tid] = (tid < NB) ? g_blocksums[tid] : 0.0f;
        __syncthreads();
        for (int s = NT / 2; s > 0; s >>= 1) {
            if (tid < s) s_ax[tid] += s_ax[tid + s];
            __syncthreads();
        }
        if (tid == 0) out[0] = s_ax[0] / (float)N1;
    }
}

// ================= launch =================
extern "C" void kernel_launch(void* const* d_in, const int* in_sizes, int n_in,
                              void* d_out, int out_size)
{
    const float* pos1 = (const float*)d_in[0];
    const float* pos2 = (const float*)d_in[1];
    float* out = (float*)d_out;

    const int N1 = in_sizes[0] / 2;
    const int N2 = in_sizes[1] / 2;

    nn_fused<<<NB, NT>>>(pos1, pos2, out, N1, N2);
}

// round 14
// speedup vs baseline: 1.7492x; 1.1999x over previous
#include <cuda_runtime.h>
#include <math_constants.h>

#define GRID 128
#define NCELLS (GRID * GRID)     // 16384
#define MAXN2 16384
#define MAXN1 16384
#define NB 256                   // blocks (co-resident: 2/SM on 148 SMs)
#define NT 256                   // threads per block
#define CPB (NCELLS / NB)        // 64 cells per block
#define FULLMASK 0xffffffffu

// ---------------- device scratch (no allocations allowed) ----------------
__device__ int    g_count[NCELLS];
__device__ int    g_start[NCELLS];   // global exclusive prefix of counts
__device__ int    g_cursor[NCELLS];
__device__ float2 g_sorted[MAXN2];
__device__ float  g_nearest[MAXN1];
__device__ float  g_bxm[NB], g_bym[NB], g_bxM[NB], g_byM[NB];
__device__ int    g_bsum[NB];
__device__ float  g_blocksums[NB];
__device__ int    g_qcount = 0;
__device__ int    g_bar_count = 0;
__device__ int    g_bar_gen   = 0;

// ---------------- software grid barrier (generation counter) ----------------
__device__ __forceinline__ void grid_barrier()
{
    __syncthreads();
    if (threadIdx.x == 0) {
        __threadfence();
        const int gen = *((volatile int*)&g_bar_gen);
        if (atomicAdd(&g_bar_count, 1) == NB - 1) {
            atomicExch(&g_bar_count, 0);
            __threadfence();
            *((volatile int*)&g_bar_gen) = gen + 1;
        } else {
            while (*((volatile int*)&g_bar_gen) == gen) { }
            __threadfence();
        }
    }
    __syncthreads();
}

__device__ __forceinline__ int cell_of(float v, float v0, float s)
{
    int c = (int)((v - v0) * s);
    c = c < 0 ? 0 : c;
    return c > GRID - 1 ? GRID - 1 : c;
}

// warp-cooperative scan of contiguous run [s, e): lanes stride, coalesced
__device__ __forceinline__ void scan_run_warp(int s, int e, int lane,
                                              float qx, float qy, float& best)
{
    for (int k = s + lane; k < e; k += 32) {
        const float2 p = g_sorted[k];
        const float dx = qx - p.x;
        const float dy = qy - p.y;
        best = fminf(best, fmaf(dx, dx, dy * dy));
    }
}

__device__ __forceinline__ float warp_min(float v)
{
#pragma unroll
    for (int off = 16; off > 0; off >>= 1)
        v = fminf(v, __shfl_xor_sync(FULLMASK, v, off));
    return v;
}

// scan all runs whose bounds sit in (s,e) across lanes; empty lanes have e<=s
__device__ __forceinline__ void scan_ballot(int s, int e, int lane,
                                            float qx, float qy, float& best)
{
    unsigned m = __ballot_sync(FULLMASK, e > s);
    while (m) {
        const int src = __ffs(m) - 1;
        m &= m - 1;
        const int ss = __shfl_sync(FULLMASK, s, src);
        const int ee = __shfl_sync(FULLMASK, e, src);
        scan_run_warp(ss, ee, lane, qx, qy, best);
    }
}

// ================= the single fused kernel =================
__global__ void __launch_bounds__(NT, 2) nn_fused(
    const float* __restrict__ pos1,
    const float* __restrict__ pos2,
    float* __restrict__ out,
    int N1, int N2)
{
    __shared__ float s_ax[NT], s_ay[NT], s_bx[NT], s_by[NT];
    __shared__ int   s_scan[NT];
    __shared__ float s_box[5];
    __shared__ int   s_off;

    const int tid = threadIdx.x;
    const int b   = blockIdx.x;
    const int gid = b * NT + tid;
    const int gstride = NB * NT;
    const int lane = tid & 31;

    // ---------- Phase 0: zero counts, reset steal counter, bbox partials ----------
    for (int c = gid; c < NCELLS; c += gstride) g_count[c] = 0;
    if (gid == 0) g_qcount = 0;

    {
        float xm = CUDART_INF_F, ym = CUDART_INF_F;
        float xM = -CUDART_INF_F, yM = -CUDART_INF_F;
        for (int i = gid; i < N2 && i < MAXN2; i += gstride) {
            const float2 p = reinterpret_cast<const float2*>(pos2)[i];
            xm = fminf(xm, p.x); xM = fmaxf(xM, p.x);
            ym = fminf(ym, p.y); yM = fmaxf(yM, p.y);
        }
        s_ax[tid] = xm; s_ay[tid] = ym; s_bx[tid] = xM; s_by[tid] = yM;
        __syncthreads();
        for (int s = NT / 2; s > 0; s >>= 1) {
            if (tid < s) {
                s_ax[tid] = fminf(s_ax[tid], s_ax[tid + s]);
                s_ay[tid] = fminf(s_ay[tid], s_ay[tid + s]);
                s_bx[tid] = fmaxf(s_bx[tid], s_bx[tid + s]);
                s_by[tid] = fmaxf(s_by[tid], s_by[tid + s]);
            }
            __syncthreads();
        }
        if (tid == 0) {
            g_bxm[b] = s_ax[0]; g_bym[b] = s_ay[0];
            g_bxM[b] = s_bx[0]; g_byM[b] = s_by[0];
        }
    }
    grid_barrier();   // (1)

    // ---------- Phase 1: finalize box (redundant per block) + count ----------
    {
        s_ax[tid] = (tid < NB) ? g_bxm[tid] : CUDART_INF_F;
        s_ay[tid] = (tid < NB) ? g_bym[tid] : CUDART_INF_F;
        s_bx[tid] = (tid < NB) ? g_bxM[tid] : -CUDART_INF_F;
        s_by[tid] = (tid < NB) ? g_byM[tid] : -CUDART_INF_F;
        __syncthreads();
        for (int s = NT / 2; s > 0; s >>= 1) {
            if (tid < s) {
                s_ax[tid] = fminf(s_ax[tid], s_ax[tid + s]);
                s_ay[tid] = fminf(s_ay[tid], s_ay[tid + s]);
                s_bx[tid] = fmaxf(s_bx[tid], s_bx[tid + s]);
                s_by[tid] = fmaxf(s_by[tid], s_by[tid + s]);
            }
            __syncthreads();
        }
        if (tid == 0) {
            const float x0 = s_ax[0], y0 = s_ay[0];
            const float ex = fmaxf(s_bx[0] - x0, 1e-6f);
            const float ey = fmaxf(s_by[0] - y0, 1e-6f);
            s_box[0] = x0;
            s_box[1] = y0;
            s_box[2] = (float)GRID / ex;
            s_box[3] = (float)GRID / ey;
            s_box[4] = fminf(ex / (float)GRID, ey / (float)GRID);
        }
        __syncthreads();
    }
    const float x0 = s_box[0], y0 = s_box[1];
    const float sx = s_box[2], sy = s_box[3];
    const float cwmin = s_box[4];
    const int n2c = (N2 < MAXN2) ? N2 : MAXN2;

    for (int i = gid; i < n2c; i += gstride) {
        const float2 p = reinterpret_cast<const float2*>(pos2)[i];
        const int cx = cell_of(p.x, x0, sx);
        const int cy = cell_of(p.y, y0, sy);
        atomicAdd(&g_count[cy * GRID + cx], 1);
    }
    grid_barrier();   // (2)

    // ---------- Phase 2: per-block scan of CPB cells ----------
    {
        int myc = 0;
        if (tid < CPB) myc = g_count[b * CPB + tid];
        s_scan[tid] = (tid < CPB) ? myc : 0;
        __syncthreads();
        for (int off = 1; off < CPB; off <<= 1) {
            int v = (tid >= off && tid < CPB) ? s_scan[tid - off] : 0;
            __syncthreads();
            if (tid < CPB) s_scan[tid] += v;
            __syncthreads();
        }
        if (tid < CPB) g_start[b * CPB + tid] = s_scan[tid] - myc;  // local exclusive
        if (tid == CPB - 1) g_bsum[b] = s_scan[tid];                // block total
    }
    grid_barrier();   // (3)

    // ---------- Phase 3: redundant scan of block totals + fixup ----------
    {
        s_scan[tid] = (tid < NB) ? g_bsum[tid] : 0;
        __syncthreads();
        for (int off = 1; off < NB; off <<= 1) {
            int v = (tid >= off && tid < NB) ? s_scan[tid - off] : 0;
            __syncthreads();
            if (tid < NB) s_scan[tid] += v;
            __syncthreads();
        }
        if (tid == 0) s_off = (b == 0) ? 0 : s_scan[b - 1];
        __syncthreads();
        const int off = s_off;
        if (tid < CPB) {
            const int base = g_start[b * CPB + tid] + off;
            g_start[b * CPB + tid]  = base;
            g_cursor[b * CPB + tid] = base;
        }
    }
    grid_barrier();   // (4)

    // ---------- Phase 4: scatter ----------
    for (int i = gid; i < n2c; i += gstride) {
        const float2 p = reinterpret_cast<const float2*>(pos2)[i];
        const int cx = cell_of(p.x, x0, sx);
        const int cy = cell_of(p.y, y0, sy);
        const int pos = atomicAdd(&g_cursor[cy * GRID + cx], 1);
        g_sorted[pos] = p;
    }
    grid_barrier();   // (5)

    // ---------- Phase 5: warp-cooperative queries (work stealing) ----------
    {
        while (true) {
            int i = 0;
            if (lane == 0) i = atomicAdd(&g_qcount, 1);
            i = __shfl_sync(FULLMASK, i, 0);
            if (i >= N1) break;

            const float2 q = reinterpret_cast<const float2*>(pos1)[i];
            const float qx = q.x, qy = q.y;
            const int cx = cell_of(qx, x0, sx);
            const int cy = cell_of(qy, y0, sy);

            float best = CUDART_INF_F;

            // initial 3x3 square: up to 3 row-runs, bounds fetched lane-parallel
            {
                const int xlo = max(cx - 1, 0), xhi = min(cx + 1, GRID - 1);
                const int ylo = max(cy - 1, 0), yhi = min(cy + 1, GRID - 1);
                const int nrows = yhi - ylo + 1;
                int s = 0, e = 0;
                if (lane < nrows) {
                    const int c0 = (ylo + lane) * GRID + xlo;
                    const int c1 = (ylo + lane) * GRID + xhi;
                    s = g_start[c0];
                    e = (c1 == NCELLS - 1) ? n2c : g_start[c1 + 1];
                }
                scan_ballot(s, e, lane, qx, qy, best);
            }

            float red = warp_min(best);
            int r = 1;
            while (true) {
                // square radius r complete: unexamined cells at Chebyshev >= r+1
                const float bd = (float)r * cwmin;
                if (red <= bd * bd) break;
                if (cx - r <= 0 && cy - r <= 0 &&
                    cx + r >= GRID - 1 && cy + r >= GRID - 1) break;  // exhausted
                r += 1;

                // ring at Chebyshev distance r: enumerate runs, lane-parallel bounds
                const int xlo = max(cx - r, 0), xhi = min(cx + r, GRID - 1);
                const int ysLo = max(cy - r + 1, 0), ysHi = min(cy + r - 1, GRID - 1);
                const int nys  = (ysHi >= ysLo) ? (ysHi - ysLo + 1) : 0;
                const int hasT = (cy - r >= 0) ? 1 : 0;
                const int hasB = (cy + r <= GRID - 1) ? 1 : 0;
                const int hasL = (cx - r >= 0) ? 1 : 0;
                const int hasR = (cx + r <= GRID - 1) ? 1 : 0;
                const int nruns = hasT + hasB + (hasL + hasR) * nys;

                for (int base = 0; base < nruns; base += 32) {
                    const int ridx = base + lane;
                    int s = 0, e = 0;
                    if (ridx < nruns) {
                        int t = ridx;
                        int c0, c1;
                        if (hasT && t == 0) {
                            c0 = (cy - r) * GRID + xlo; c1 = (cy - r) * GRID + xhi;
                        } else {
                            t -= hasT;
                            if (hasB && t == 0) {
                                c0 = (cy + r) * GRID + xlo; c1 = (cy + r) * GRID + xhi;
                            } else {
                                t -= hasB;
                                if (hasL && t < nys) {
                                    c0 = (ysLo + t) * GRID + (cx - r); c1 = c0;
                                } else {
                                    if (hasL) t -= nys;
                                    c0 = (ysLo + t) * GRID + (cx + r); c1 = c0;
                                }
                            }
                        }
                        s = g_start[c0];
                        e = (c1 == NCELLS - 1) ? n2c : g_start[c1 + 1];
                    }
                    scan_ballot(s, e, lane, qx, qy, best);
                }
                red = warp_min(best);
            }

            if (lane == 0) g_nearest[i] = sqrtf(red);
        }
    }
    grid_barrier();   // (6)

    // ---------- Phase 6a: deterministic block partial sums over g_nearest ----------
    {
        float acc = 0.0f;
        for (int i = gid; i < N1 && i < MAXN1; i += gstride) acc += g_nearest[i];
        s_ax[tid] = acc;
        __syncthreads();
        for (int s = NT / 2; s > 0; s >>= 1) {
            if (tid < s) s_ax[tid] += s_ax[tid + s];
            __syncthreads();
        }
        if (tid == 0) g_blocksums[b] = s_ax[0];
    }
    grid_barrier();   // (7)

    // ---------- Phase 6b: final reduce (block 0) ----------
    if (b == 0) {
        s_ax[tid] = (tid < NB) ? g_blocksums[tid] : 0.0f;
        __syncthreads();
        for (int s = NT / 2; s > 0; s >>= 1) {
            if (tid < s) s_ax[tid] += s_ax[tid + s];
            __syncthreads();
        }
        if (tid == 0) out[0] = s_ax[0] / (float)N1;
    }
}

// ================= launch =================
extern "C" void kernel_launch(void* const* d_in, const int* in_sizes, int n_in,
                              void* d_out, int out_size)
{
    const float* pos1 = (const float*)d_in[0];
    const float* pos2 = (const float*)d_in[1];
    float* out = (float*)d_out;

    const int N1 = in_sizes[0] / 2;
    const int N2 = in_sizes[1] / 2;

    nn_fused<<<NB, NT>>>(pos1, pos2, out, N1, N2);
}